// round 6
// baseline (speedup 1.0000x reference)
#include <cuda_runtime.h>

// NeRF fused render: near/far -> coarse bins -> scatter inverse-CDF sampling ->
// contraction -> alpha compositing.
// One warp per ray, strided sample ownership (lane l owns samples l+32c).
// All global traffic line-exact: rgb via 3x LDG.128, output row staged in smem
// (conflict-free stride-3 STS) and stored as 97 coalesced STG.128.

constexpr int T0 = 64;     // coarse intervals
constexpr int TF = 128;    // fine samples
constexpr int OUTW = 4 + 3 * TF;     // 388 floats per ray
constexpr int WPB = 8;               // warps per block
constexpr unsigned FULL = 0xffffffffu;

__global__ __launch_bounds__(WPB * 32, 8)
void nerf_render_kernel(const float* __restrict__ rays_o,
                        const float* __restrict__ rays_d,
                        const float* __restrict__ aabb,
                        const float* __restrict__ wc,     // [N, 64]
                        const float* __restrict__ sigmas, // [N, 128]
                        const float* __restrict__ rgbs,   // [N, 128, 3]
                        float* __restrict__ out,          // [N, 388]
                        int N)
{
    __shared__ float s_zed[WPB][TF + 4];       // 129 fine edges (+pad)
    __shared__ float s_w[WPB][TF];             // per-sample weights
    __shared__ float s_stage[WPB][OUTW + 4];   // output row staging (392 floats)

    const int warp = threadIdx.x >> 5;
    const int lane = threadIdx.x & 31;
    const int ray  = blockIdx.x * WPB + warp;
    if (ray >= N) return;

    // ---- ray + aabb ----
    const float ox = rays_o[3 * ray + 0];
    const float oy = rays_o[3 * ray + 1];
    const float oz = rays_o[3 * ray + 2];
    const float dx = rays_d[3 * ray + 0];
    const float dy = rays_d[3 * ray + 1];
    const float dz = rays_d[3 * ray + 2];

    const float ix = 1.0f / (dx + 1e-15f);
    const float iy = 1.0f / (dy + 1e-15f);
    const float iz = 1.0f / (dz + 1e-15f);
    const float t0x = (aabb[0] - ox) * ix, t1x = (aabb[3] - ox) * ix;
    const float t0y = (aabb[1] - oy) * iy, t1y = (aabb[4] - oy) * iy;
    const float t0z = (aabb[2] - oz) * iz, t1z = (aabb[5] - oz) * iz;

    float nearv = fmaxf(fmaxf(fminf(t0x, t1x), fminf(t0y, t1y)), fminf(t0z, t1z));
    float farv  = fminf(fminf(fmaxf(t0x, t1x), fmaxf(t0y, t1y)), fmaxf(t0z, t1z));
    if (farv < nearv) { nearv = 1e9f; farv = 1e9f; }
    nearv = fmaxf(nearv, 0.05f);
    const float span = farv - nearv;
    const float db = span * (1.0f / 64.0f);   // coarse bin width (constant)

    // ---- CDF of (weights + 0.01), normalized, clipped to 1 (registers only) ----
    float s0 = wc[(size_t)ray * T0 + lane]      + 0.01f;
    float s1 = wc[(size_t)ray * T0 + 32 + lane] + 0.01f;

    #pragma unroll
    for (int o = 1; o < 32; o <<= 1) {
        float v = __shfl_up_sync(FULL, s0, o);
        if (lane >= o) s0 += v;
    }
    #pragma unroll
    for (int o = 1; o < 32; o <<= 1) {
        float v = __shfl_up_sync(FULL, s1, o);
        if (lane >= o) s1 += v;
    }
    s1 += __shfl_sync(FULL, s0, 31);
    const float inv_tot = 1.0f / __shfl_sync(FULL, s1, 31);

    // lane l holds C[l+1] = ca and C[l+33] = cb  (C[0] = 0)
    const float ca = fminf(s0 * inv_tot, 1.0f);
    const float cb = fminf(s1 * inv_tot, 1.0f);
    const float ca_up = __shfl_up_sync(FULL, ca, 1);
    const float cb_up = __shfl_up_sync(FULL, cb, 1);
    const float ca31  = __shfl_sync(FULL, ca, 31);

    float* zed = s_zed[warp];

    // ---- scatter fine edges: interval k covers u in [C[k], C[k+1]) ----
    #pragma unroll
    for (int h = 0; h < 2; ++h) {
        const int k = h * 32 + lane;
        const float c0 = (h == 0) ? ((lane == 0) ? 0.0f : ca_up)
                                  : ((lane == 0) ? ca31 : cb_up);
        const float c1 = (h == 0) ? ca : cb;

        int j0 = (int)ceilf(fmaf(129.0f, c0, -0.5f));
        int j1 = (k == 63) ? 129 : (int)ceilf(fmaf(129.0f, c1, -0.5f));
        j0 = max(j0, 0);
        j1 = min(j1, 129);

        const float inv_den = __fdividef(1.0f, fmaxf(c1 - c0, 1e-12f));
        const float b0 = fmaf(db, (float)k, nearv);

        for (int j = j0; j < j1; ++j) {
            const float u = (j + 0.5f) * (1.0f / 129.0f);
            float t = fminf(fmaxf((u - c0) * inv_den, 0.0f), 1.0f);
            zed[j] = fmaf(t, db, b0);
        }
    }
    __syncwarp();

    // ---- per-chunk compositing weights + contraction into smem stage ----
    const float* sgp = sigmas + (size_t)ray * TF;
    float* wrow = s_w[warp];
    float* stage = s_stage[warp];

    float dep = 0.0f;
    float carry = 1.0f;

    #pragma unroll
    for (int c = 0; c < 4; ++c) {
        const int si = 32 * c + lane;            // this lane's sample index
        const float zl = zed[si];
        const float zr = zed[si + 1];

        const float delta = zr - zl;
        const float zm = 0.5f * (zl + zr);
        const float sg = sgp[si];
        const float alpha = 1.0f - __expf(-sg * delta);
        const float v = 1.0f - alpha + 1e-10f;

        // warp inclusive multiplicative scan of v
        float incl = v;
        #pragma unroll
        for (int o = 1; o < 32; o <<= 1) {
            float p = __shfl_up_sync(FULL, incl, o);
            if (lane >= o) incl *= p;
        }
        float excl = __shfl_up_sync(FULL, incl, 1);
        if (lane == 0) excl = 1.0f;
        const float chunk_tot = __shfl_sync(FULL, incl, 31);

        const float wgt = alpha * carry * excl;
        carry *= chunk_tot;

        wrow[si] = wgt;                          // stride-1 STS, conflict-free
        dep += wgt * zm;

        // position + contraction
        float x = fmaf(dx, zm, ox);
        float y = fmaf(dy, zm, oy);
        float z = fmaf(dz, zm, oz);
        const float ax = fabsf(x), ay = fabsf(y), az = fabsf(z);
        const float mag = fmaxf(ax, fmaxf(ay, az));
        float cx = x, cy = y, cz = z;
        if (mag >= 1.0f) {
            const float im = 1.0f / mag;
            const float sm = (2.0f - im) * im;
            cx = x * im; cy = y * im; cz = z * im;
            if (ax == mag)      cx = x * sm;   // argmax tie-break order x,y,z
            else if (ay == mag) cy = y * sm;
            else                cz = z * sm;
        }
        // stride-3 word STS: gcd(3,32)=1 -> conflict-free
        stage[4 + 3 * si + 0] = cx;
        stage[4 + 3 * si + 1] = cy;
        stage[4 + 3 * si + 2] = cz;
    }
    __syncwarp();

    // ---- rgb dot-product in float4 domain (line-exact loads) ----
    const float4* rg4 = reinterpret_cast<const float4*>(rgbs + (size_t)ray * TF * 3);
    float img0 = 0.0f, img1 = 0.0f, img2 = 0.0f;

    #pragma unroll
    for (int h = 0; h < 3; ++h) {
        const int q = lane + 32 * h;             // float4 index
        const float4 r = rg4[q];
        const int p = 4 * q;                     // flat float index
        const float vals[4] = {r.x, r.y, r.z, r.w};
        #pragma unroll
        for (int e = 0; e < 4; ++e) {
            const int pe = p + e;
            const int s = pe / 3;                // sample index
            const int ch = pe - 3 * s;           // channel
            const float t = wrow[s] * vals[e];
            if      (ch == 0) img0 += t;
            else if (ch == 1) img1 += t;
            else              img2 += t;
        }
    }

    // ---- warp reduction for image + depth ----
    #pragma unroll
    for (int o = 16; o > 0; o >>= 1) {
        img0 += __shfl_down_sync(FULL, img0, o);
        img1 += __shfl_down_sync(FULL, img1, o);
        img2 += __shfl_down_sync(FULL, img2, o);
        dep  += __shfl_down_sync(FULL, dep,  o);
    }
    if (lane == 0) {
        stage[0] = img0;
        stage[1] = img1;
        stage[2] = img2;
        stage[3] = dep;
    }
    __syncwarp();

    // ---- coalesced store of the full 388-float output row (97 float4) ----
    {
        const float4* src4 = reinterpret_cast<const float4*>(stage);
        float4* dst4 = reinterpret_cast<float4*>(out + (size_t)ray * OUTW);
        dst4[lane]      = src4[lane];
        dst4[lane + 32] = src4[lane + 32];
        dst4[lane + 64] = src4[lane + 64];
        if (lane == 0) dst4[96] = src4[96];
    }
}

extern "C" void kernel_launch(void* const* d_in, const int* in_sizes, int n_in,
                              void* d_out, int out_size)
{
    const float* rays_o = (const float*)d_in[0];
    const float* rays_d = (const float*)d_in[1];
    const float* aabb   = (const float*)d_in[2];
    const float* wc     = (const float*)d_in[3];
    const float* sigmas = (const float*)d_in[4];
    const float* rgbs   = (const float*)d_in[5];
    float* out = (float*)d_out;

    const int N = in_sizes[0] / 3;   // rays_o has N*3 elements
    const int blocks = (N + WPB - 1) / WPB;
    nerf_render_kernel<<<blocks, WPB * 32>>>(
        rays_o, rays_d, aabb, wc, sigmas, rgbs, out, N);
}

// round 7
// speedup vs baseline: 1.1381x; 1.1381x over previous
#include <cuda_runtime.h>

// NeRF fused render: near/far -> coarse bins -> scatter inverse-CDF sampling ->
// contraction -> alpha compositing.
// One warp per ray. Phase A: per-sample weights (strided ownership) + depth.
// Phase B: float4-granular output; xyz contraction RECOMPUTED per output
// float4 (2 samples each) so both rgb loads and xyz stores are line-exact
// 128-bit coalesced ops.

constexpr int T0 = 64;     // coarse intervals
constexpr int TF = 128;    // fine samples
constexpr int OUTW = 4 + 3 * TF;     // 388 floats per ray
constexpr int WPB = 8;               // warps per block
constexpr unsigned FULL = 0xffffffffu;

__device__ __forceinline__ void contract_pt(float zm,
                                            float ox, float oy, float oz,
                                            float dx, float dy, float dz,
                                            float& cx, float& cy, float& cz)
{
    float x = fmaf(dx, zm, ox);
    float y = fmaf(dy, zm, oy);
    float z = fmaf(dz, zm, oz);
    const float ax = fabsf(x), ay = fabsf(y), az = fabsf(z);
    const float mag = fmaxf(ax, fmaxf(ay, az));
    cx = x; cy = y; cz = z;
    if (mag >= 1.0f) {
        const float im = 1.0f / mag;
        const float sm = (2.0f - im) * im;
        cx = x * im; cy = y * im; cz = z * im;
        if (ax == mag)      cx = x * sm;   // argmax tie-break order x,y,z
        else if (ay == mag) cy = y * sm;
        else                cz = z * sm;
    }
}

__global__ __launch_bounds__(WPB * 32, 8)
void nerf_render_kernel(const float* __restrict__ rays_o,
                        const float* __restrict__ rays_d,
                        const float* __restrict__ aabb,
                        const float* __restrict__ wc,     // [N, 64]
                        const float* __restrict__ sigmas, // [N, 128]
                        const float* __restrict__ rgbs,   // [N, 128, 3]
                        float* __restrict__ out,          // [N, 388]
                        int N)
{
    __shared__ float s_zed[WPB][TF + 4];   // 129 fine edges (+pad)
    __shared__ float s_w[WPB][TF];         // per-sample composited weights

    const int warp = threadIdx.x >> 5;
    const int lane = threadIdx.x & 31;
    const int ray  = blockIdx.x * WPB + warp;
    if (ray >= N) return;

    // ---- ray + aabb ----
    const float ox = rays_o[3 * ray + 0];
    const float oy = rays_o[3 * ray + 1];
    const float oz = rays_o[3 * ray + 2];
    const float dx = rays_d[3 * ray + 0];
    const float dy = rays_d[3 * ray + 1];
    const float dz = rays_d[3 * ray + 2];

    const float ix = 1.0f / (dx + 1e-15f);
    const float iy = 1.0f / (dy + 1e-15f);
    const float iz = 1.0f / (dz + 1e-15f);
    const float t0x = (aabb[0] - ox) * ix, t1x = (aabb[3] - ox) * ix;
    const float t0y = (aabb[1] - oy) * iy, t1y = (aabb[4] - oy) * iy;
    const float t0z = (aabb[2] - oz) * iz, t1z = (aabb[5] - oz) * iz;

    float nearv = fmaxf(fmaxf(fminf(t0x, t1x), fminf(t0y, t1y)), fminf(t0z, t1z));
    float farv  = fminf(fminf(fmaxf(t0x, t1x), fmaxf(t0y, t1y)), fmaxf(t0z, t1z));
    if (farv < nearv) { nearv = 1e9f; farv = 1e9f; }
    nearv = fmaxf(nearv, 0.05f);
    const float span = farv - nearv;
    const float db = span * (1.0f / 64.0f);   // coarse bin width (constant)

    // ---- CDF of (weights + 0.01), normalized, clipped to 1 (registers only) ----
    float s0 = wc[(size_t)ray * T0 + lane]      + 0.01f;
    float s1 = wc[(size_t)ray * T0 + 32 + lane] + 0.01f;

    #pragma unroll
    for (int o = 1; o < 32; o <<= 1) {
        float v = __shfl_up_sync(FULL, s0, o);
        if (lane >= o) s0 += v;
    }
    #pragma unroll
    for (int o = 1; o < 32; o <<= 1) {
        float v = __shfl_up_sync(FULL, s1, o);
        if (lane >= o) s1 += v;
    }
    s1 += __shfl_sync(FULL, s0, 31);
    const float inv_tot = 1.0f / __shfl_sync(FULL, s1, 31);

    // lane l holds C[l+1] = ca and C[l+33] = cb  (C[0] = 0)
    const float ca = fminf(s0 * inv_tot, 1.0f);
    const float cb = fminf(s1 * inv_tot, 1.0f);
    const float ca_up = __shfl_up_sync(FULL, ca, 1);
    const float cb_up = __shfl_up_sync(FULL, cb, 1);
    const float ca31  = __shfl_sync(FULL, ca, 31);

    float* zed = s_zed[warp];

    // ---- scatter fine edges: interval k covers u in [C[k], C[k+1]) ----
    #pragma unroll
    for (int h = 0; h < 2; ++h) {
        const int k = h * 32 + lane;
        const float c0 = (h == 0) ? ((lane == 0) ? 0.0f : ca_up)
                                  : ((lane == 0) ? ca31 : cb_up);
        const float c1 = (h == 0) ? ca : cb;

        int j0 = (int)ceilf(fmaf(129.0f, c0, -0.5f));
        int j1 = (k == 63) ? 129 : (int)ceilf(fmaf(129.0f, c1, -0.5f));
        j0 = max(j0, 0);
        j1 = min(j1, 129);

        const float inv_den = __fdividef(1.0f, fmaxf(c1 - c0, 1e-12f));
        const float b0 = fmaf(db, (float)k, nearv);

        for (int j = j0; j < j1; ++j) {
            const float u = (j + 0.5f) * (1.0f / 129.0f);
            float t = fminf(fmaxf((u - c0) * inv_den, 0.0f), 1.0f);
            zed[j] = fmaf(t, db, b0);
        }
    }
    __syncwarp();

    // ---- Phase A: compositing weights (strided ownership) + depth ----
    const float* sgp = sigmas + (size_t)ray * TF;
    float* wrow = s_w[warp];

    float dep = 0.0f;
    float carry = 1.0f;

    #pragma unroll
    for (int c = 0; c < 4; ++c) {
        const int si = 32 * c + lane;
        const float zl = zed[si];
        const float zr = zed[si + 1];

        const float delta = zr - zl;
        const float zm = 0.5f * (zl + zr);
        const float sg = sgp[si];
        const float alpha = 1.0f - __expf(-sg * delta);
        const float v = 1.0f - alpha + 1e-10f;

        // warp inclusive multiplicative scan of v
        float incl = v;
        #pragma unroll
        for (int o = 1; o < 32; o <<= 1) {
            float p = __shfl_up_sync(FULL, incl, o);
            if (lane >= o) incl *= p;
        }
        float excl = __shfl_up_sync(FULL, incl, 1);
        if (lane == 0) excl = 1.0f;
        const float chunk_tot = __shfl_sync(FULL, incl, 31);

        const float wgt = alpha * carry * excl;
        carry *= chunk_tot;

        wrow[si] = wgt;                       // stride-1 STS, conflict-free
        dep += wgt * zm;
    }
    __syncwarp();

    // ---- Phase B: float4-granular rgb gather + xyz recompute + store ----
    const float4* rg4 = reinterpret_cast<const float4*>(rgbs + (size_t)ray * TF * 3);
    const size_t base = (size_t)ray * OUTW;
    float4* xo4 = reinterpret_cast<float4*>(out + base + 4);   // 16B aligned

    float img0 = 0.0f, img1 = 0.0f, img2 = 0.0f;

    #pragma unroll
    for (int h = 0; h < 3; ++h) {
        const int q = lane + 32 * h;          // output/rgb float4 index, 0..95
        const float4 r = rg4[q];
        const int p0 = 4 * q;
        const int sA = p0 / 3;                // first sample in this float4
        const int rem = p0 - 3 * sA;          // 0,1,2

        // zm for samples sA, sA+1 (zed has 129 entries; sA<=126 -> sA+2<=128)
        const float zA0 = zed[sA];
        const float zA1 = zed[sA + 1];
        const float zA2 = zed[sA + 2];
        const float zmA = 0.5f * (zA0 + zA1);
        const float zmB = 0.5f * (zA1 + zA2);

        const float wA = wrow[sA];
        const float wB = wrow[sA + 1];

        // image accumulation: channel pattern by rem
        // rem0: [A0,A1,A2,B0]  rem1: [A1,A2,B0,B1]  rem2: [A2,B0,B1,B2]
        const float s_xw = fmaf(wA, r.x, wB * r.w);          // ch: rem
        const float s_y  = ((rem == 2) ? wB : wA) * r.y;     // ch: (rem+1)%3
        const float s_z  = ((rem == 0) ? wA : wB) * r.z;     // ch: (rem+2)%3
        img0 += (rem == 0) ? s_xw : (rem == 1) ? s_z : s_y;
        img1 += (rem == 0) ? s_y  : (rem == 1) ? s_xw : s_z;
        img2 += (rem == 0) ? s_z  : (rem == 1) ? s_y : s_xw;

        // xyz: contraction for the two samples, component select by rem
        float cxA, cyA, czA, cxB, cyB, czB;
        contract_pt(zmA, ox, oy, oz, dx, dy, dz, cxA, cyA, czA);
        contract_pt(zmB, ox, oy, oz, dx, dy, dz, cxB, cyB, czB);

        const float v0 = (rem == 0) ? cxA : (rem == 1) ? cyA : czA;
        const float v1 = (rem == 0) ? cyA : (rem == 1) ? czA : cxB;
        const float v2 = (rem == 0) ? czA : (rem == 1) ? cxB : cyB;
        const float v3 = (rem == 0) ? cxB : (rem == 1) ? cyB : czB;
        xo4[q] = make_float4(v0, v1, v2, v3);
    }

    // ---- warp reduction for image + depth ----
    #pragma unroll
    for (int o = 16; o > 0; o >>= 1) {
        img0 += __shfl_down_sync(FULL, img0, o);
        img1 += __shfl_down_sync(FULL, img1, o);
        img2 += __shfl_down_sync(FULL, img2, o);
        dep  += __shfl_down_sync(FULL, dep,  o);
    }
    if (lane == 0) {
        float4 head = make_float4(img0, img1, img2, dep);
        *reinterpret_cast<float4*>(out + base) = head;
    }
}

extern "C" void kernel_launch(void* const* d_in, const int* in_sizes, int n_in,
                              void* d_out, int out_size)
{
    const float* rays_o = (const float*)d_in[0];
    const float* rays_d = (const float*)d_in[1];
    const float* aabb   = (const float*)d_in[2];
    const float* wc     = (const float*)d_in[3];
    const float* sigmas = (const float*)d_in[4];
    const float* rgbs   = (const float*)d_in[5];
    float* out = (float*)d_out;

    const int N = in_sizes[0] / 3;   // rays_o has N*3 elements
    const int blocks = (N + WPB - 1) / WPB;
    nerf_render_kernel<<<blocks, WPB * 32>>>(
        rays_o, rays_d, aabb, wc, sigmas, rgbs, out, N);
}

// round 8
// speedup vs baseline: 1.4095x; 1.2385x over previous
#include <cuda_runtime.h>

// NeRF fused render: near/far -> coarse bins -> scatter inverse-CDF sampling ->
// contraction -> alpha compositing.
// One warp per ray. BLOCKED sample ownership (lane owns samples 4l..4l+3):
//  - compositing via exp-difference: w[s] = exp(-S_s) - exp(-S_{s+1}),
//    needing ONE additive warp scan instead of four multiplicative ones.
//  - sigma 1x LDG.128, rgb 3x LDG.128 (compile-time channel map),
//    xyz 3x STG.128 straight from registers. Minimal instruction count.

constexpr int T0 = 64;     // coarse intervals
constexpr int TF = 128;    // fine samples
constexpr int OUTW = 4 + 3 * TF;     // 388 floats per ray
constexpr int WPB = 8;               // warps per block
constexpr unsigned FULL = 0xffffffffu;

__device__ __forceinline__ void contract_pt(float zm,
                                            float ox, float oy, float oz,
                                            float dx, float dy, float dz,
                                            float& cx, float& cy, float& cz)
{
    float x = fmaf(dx, zm, ox);
    float y = fmaf(dy, zm, oy);
    float z = fmaf(dz, zm, oz);
    const float ax = fabsf(x), ay = fabsf(y), az = fabsf(z);
    const float mag = fmaxf(ax, fmaxf(ay, az));
    cx = x; cy = y; cz = z;
    if (mag >= 1.0f) {
        const float im = 1.0f / mag;
        const float sm = (2.0f - im) * im;
        cx = x * im; cy = y * im; cz = z * im;
        if (ax == mag)      cx = x * sm;   // argmax tie-break order x,y,z
        else if (ay == mag) cy = y * sm;
        else                cz = z * sm;
    }
}

__global__ __launch_bounds__(WPB * 32, 8)
void nerf_render_kernel(const float* __restrict__ rays_o,
                        const float* __restrict__ rays_d,
                        const float* __restrict__ aabb,
                        const float* __restrict__ wc,     // [N, 64]
                        const float* __restrict__ sigmas, // [N, 128]
                        const float* __restrict__ rgbs,   // [N, 128, 3]
                        float* __restrict__ out,          // [N, 388]
                        int N)
{
    __shared__ __align__(16) float s_zed[WPB][TF + 8];   // 129 fine edges (+pad)

    const int warp = threadIdx.x >> 5;
    const int lane = threadIdx.x & 31;
    const int ray  = blockIdx.x * WPB + warp;
    if (ray >= N) return;

    // ---- ray + aabb ----
    const float ox = rays_o[3 * ray + 0];
    const float oy = rays_o[3 * ray + 1];
    const float oz = rays_o[3 * ray + 2];
    const float dx = rays_d[3 * ray + 0];
    const float dy = rays_d[3 * ray + 1];
    const float dz = rays_d[3 * ray + 2];

    const float ix = 1.0f / (dx + 1e-15f);
    const float iy = 1.0f / (dy + 1e-15f);
    const float iz = 1.0f / (dz + 1e-15f);
    const float t0x = (aabb[0] - ox) * ix, t1x = (aabb[3] - ox) * ix;
    const float t0y = (aabb[1] - oy) * iy, t1y = (aabb[4] - oy) * iy;
    const float t0z = (aabb[2] - oz) * iz, t1z = (aabb[5] - oz) * iz;

    float nearv = fmaxf(fmaxf(fminf(t0x, t1x), fminf(t0y, t1y)), fminf(t0z, t1z));
    float farv  = fminf(fminf(fmaxf(t0x, t1x), fmaxf(t0y, t1y)), fmaxf(t0z, t1z));
    if (farv < nearv) { nearv = 1e9f; farv = 1e9f; }
    nearv = fmaxf(nearv, 0.05f);
    const float span = farv - nearv;
    const float db = span * (1.0f / 64.0f);   // coarse bin width (constant)

    // ---- CDF of (weights + 0.01), normalized, clipped to 1 (registers only) ----
    float s0 = wc[(size_t)ray * T0 + lane]      + 0.01f;
    float s1 = wc[(size_t)ray * T0 + 32 + lane] + 0.01f;

    #pragma unroll
    for (int o = 1; o < 32; o <<= 1) {
        float v = __shfl_up_sync(FULL, s0, o);
        if (lane >= o) s0 += v;
    }
    #pragma unroll
    for (int o = 1; o < 32; o <<= 1) {
        float v = __shfl_up_sync(FULL, s1, o);
        if (lane >= o) s1 += v;
    }
    s1 += __shfl_sync(FULL, s0, 31);
    const float inv_tot = 1.0f / __shfl_sync(FULL, s1, 31);

    // lane l holds C[l+1] = ca and C[l+33] = cb  (C[0] = 0)
    const float ca = fminf(s0 * inv_tot, 1.0f);
    const float cb = fminf(s1 * inv_tot, 1.0f);
    const float ca_up = __shfl_up_sync(FULL, ca, 1);
    const float cb_up = __shfl_up_sync(FULL, cb, 1);
    const float ca31  = __shfl_sync(FULL, ca, 31);

    float* zed = s_zed[warp];

    // ---- scatter fine edges: interval k covers u in [C[k], C[k+1]) ----
    #pragma unroll
    for (int h = 0; h < 2; ++h) {
        const int k = h * 32 + lane;
        const float c0 = (h == 0) ? ((lane == 0) ? 0.0f : ca_up)
                                  : ((lane == 0) ? ca31 : cb_up);
        const float c1 = (h == 0) ? ca : cb;

        int j0 = (int)ceilf(fmaf(129.0f, c0, -0.5f));
        int j1 = (k == 63) ? 129 : (int)ceilf(fmaf(129.0f, c1, -0.5f));
        j0 = max(j0, 0);
        j1 = min(j1, 129);

        const float inv_den = __fdividef(1.0f, fmaxf(c1 - c0, 1e-12f));
        const float b0 = fmaf(db, (float)k, nearv);

        for (int j = j0; j < j1; ++j) {
            const float u = (j + 0.5f) * (1.0f / 129.0f);
            float t = fminf(fmaxf((u - c0) * inv_den, 0.0f), 1.0f);
            zed[j] = fmaf(t, db, b0);
        }
    }
    __syncwarp();

    // ---- blocked compositing: lane owns samples 4l..4l+3 ----
    const float4 z4 = *reinterpret_cast<const float4*>(&zed[4 * lane]);
    const float ztop = zed[TF];                         // zed[128], broadcast
    const float znxt = __shfl_down_sync(FULL, z4.x, 1); // next lane's first edge
    const float e4 = (lane == 31) ? ztop : znxt;

    const float4 sg4 = *reinterpret_cast<const float4*>(
        sigmas + (size_t)ray * TF + 4 * lane);

    const float d0 = z4.y - z4.x;
    const float d1 = z4.z - z4.y;
    const float d2 = z4.w - z4.z;
    const float d3 = e4   - z4.w;

    const float q0 = sg4.x * d0;
    const float q1 = sg4.y * d1;
    const float q2 = sg4.z * d2;
    const float q3 = sg4.w * d3;

    const float p1 = q0;
    const float p2 = q0 + q1;
    const float p3 = p2 + q2;
    const float Tl = p3 + q3;               // lane-local optical depth

    // single additive warp scan over lane totals
    float incl = Tl;
    #pragma unroll
    for (int o = 1; o < 32; o <<= 1) {
        float v = __shfl_up_sync(FULL, incl, o);
        if (lane >= o) incl += v;
    }
    float S0 = __shfl_up_sync(FULL, incl, 1);
    if (lane == 0) S0 = 0.0f;

    const float E0 = __expf(-S0);
    const float E1 = __expf(-(S0 + p1));
    const float E2 = __expf(-(S0 + p2));
    const float E3 = __expf(-(S0 + p3));
    const float E4 = __expf(-(S0 + Tl));

    const float w0 = E0 - E1;
    const float w1 = E1 - E2;
    const float w2 = E2 - E3;
    const float w3 = E3 - E4;

    const float zm0 = 0.5f * (z4.x + z4.y);
    const float zm1 = 0.5f * (z4.y + z4.z);
    const float zm2 = 0.5f * (z4.z + z4.w);
    const float zm3 = 0.5f * (z4.w + e4);

    float dep = w0 * zm0 + w1 * zm1 + w2 * zm2 + w3 * zm3;

    // ---- rgb: 3x LDG.128, compile-time channel mapping ----
    const float4* rg4 = reinterpret_cast<const float4*>(
        rgbs + (size_t)ray * TF * 3) + 3 * lane;
    const float4 f0 = rg4[0];
    const float4 f1 = rg4[1];
    const float4 f2 = rg4[2];

    float img0 = w0 * f0.x + w1 * f0.w + w2 * f1.z + w3 * f2.y;
    float img1 = w0 * f0.y + w1 * f1.x + w2 * f1.w + w3 * f2.z;
    float img2 = w0 * f0.z + w1 * f1.y + w2 * f2.x + w3 * f2.w;

    // ---- contraction + packed xyz stores (3x STG.128) ----
    float c0x, c0y, c0z, c1x, c1y, c1z, c2x, c2y, c2z, c3x, c3y, c3z;
    contract_pt(zm0, ox, oy, oz, dx, dy, dz, c0x, c0y, c0z);
    contract_pt(zm1, ox, oy, oz, dx, dy, dz, c1x, c1y, c1z);
    contract_pt(zm2, ox, oy, oz, dx, dy, dz, c2x, c2y, c2z);
    contract_pt(zm3, ox, oy, oz, dx, dy, dz, c3x, c3y, c3z);

    const size_t base = (size_t)ray * OUTW;
    float4* xo4 = reinterpret_cast<float4*>(out + base + 4) + 3 * lane;
    xo4[0] = make_float4(c0x, c0y, c0z, c1x);
    xo4[1] = make_float4(c1y, c1z, c2x, c2y);
    xo4[2] = make_float4(c2z, c3x, c3y, c3z);

    // ---- warp reduction for image + depth ----
    #pragma unroll
    for (int o = 16; o > 0; o >>= 1) {
        img0 += __shfl_down_sync(FULL, img0, o);
        img1 += __shfl_down_sync(FULL, img1, o);
        img2 += __shfl_down_sync(FULL, img2, o);
        dep  += __shfl_down_sync(FULL, dep,  o);
    }
    if (lane == 0) {
        float4 head = make_float4(img0, img1, img2, dep);
        *reinterpret_cast<float4*>(out + base) = head;
    }
}

extern "C" void kernel_launch(void* const* d_in, const int* in_sizes, int n_in,
                              void* d_out, int out_size)
{
    const float* rays_o = (const float*)d_in[0];
    const float* rays_d = (const float*)d_in[1];
    const float* aabb   = (const float*)d_in[2];
    const float* wc     = (const float*)d_in[3];
    const float* sigmas = (const float*)d_in[4];
    const float* rgbs   = (const float*)d_in[5];
    float* out = (float*)d_out;

    const int N = in_sizes[0] / 3;   // rays_o has N*3 elements
    const int blocks = (N + WPB - 1) / WPB;
    nerf_render_kernel<<<blocks, WPB * 32>>>(
        rays_o, rays_d, aabb, wc, sigmas, rgbs, out, N);
}

// round 9
// speedup vs baseline: 1.5299x; 1.0854x over previous
#include <cuda_runtime.h>

// NeRF fused render: near/far -> coarse bins -> scatter inverse-CDF sampling ->
// contraction -> alpha compositing.
// One warp per ray. Blocked sample ownership (lane owns samples 4l..4l+3).
// Compositing via exp-difference (one additive warp scan). CDF intervals
// pair-owned per lane (no neighbor shuffles). All divisions via rcp.approx.

constexpr int T0 = 64;     // coarse intervals
constexpr int TF = 128;    // fine samples
constexpr int OUTW = 4 + 3 * TF;     // 388 floats per ray
constexpr int WPB = 8;               // warps per block
constexpr unsigned FULL = 0xffffffffu;

__device__ __forceinline__ float frcp(float x) {
    float r;
    asm("rcp.approx.f32 %0, %1;" : "=f"(r) : "f"(x));
    return r;
}

__device__ __forceinline__ void contract_pt(float zm,
                                            float ox, float oy, float oz,
                                            float dx, float dy, float dz,
                                            float& cx, float& cy, float& cz)
{
    float x = fmaf(dx, zm, ox);
    float y = fmaf(dy, zm, oy);
    float z = fmaf(dz, zm, oz);
    const float ax = fabsf(x), ay = fabsf(y), az = fabsf(z);
    const float mag = fmaxf(ax, fmaxf(ay, az));
    cx = x; cy = y; cz = z;
    if (mag >= 1.0f) {
        const float im = frcp(mag);
        const float sm = (2.0f - im) * im;
        cx = x * im; cy = y * im; cz = z * im;
        if (ax == mag)      cx = x * sm;   // argmax tie-break order x,y,z
        else if (ay == mag) cy = y * sm;
        else                cz = z * sm;
    }
}

__global__ __launch_bounds__(WPB * 32, 8)
void nerf_render_kernel(const float* __restrict__ rays_o,
                        const float* __restrict__ rays_d,
                        const float* __restrict__ aabb,
                        const float* __restrict__ wc,     // [N, 64]
                        const float* __restrict__ sigmas, // [N, 128]
                        const float* __restrict__ rgbs,   // [N, 128, 3]
                        float* __restrict__ out,          // [N, 388]
                        int N)
{
    __shared__ __align__(16) float s_zed[WPB][TF + 8];   // 129 fine edges (+pad)

    const int warp = threadIdx.x >> 5;
    const int lane = threadIdx.x & 31;
    const int ray  = blockIdx.x * WPB + warp;
    if (ray >= N) return;

    // ---- ray + aabb ----
    const float ox = rays_o[3 * ray + 0];
    const float oy = rays_o[3 * ray + 1];
    const float oz = rays_o[3 * ray + 2];
    const float dx = rays_d[3 * ray + 0];
    const float dy = rays_d[3 * ray + 1];
    const float dz = rays_d[3 * ray + 2];

    const float ix = frcp(dx + 1e-15f);
    const float iy = frcp(dy + 1e-15f);
    const float iz = frcp(dz + 1e-15f);
    const float t0x = (aabb[0] - ox) * ix, t1x = (aabb[3] - ox) * ix;
    const float t0y = (aabb[1] - oy) * iy, t1y = (aabb[4] - oy) * iy;
    const float t0z = (aabb[2] - oz) * iz, t1z = (aabb[5] - oz) * iz;

    float nearv = fmaxf(fmaxf(fminf(t0x, t1x), fminf(t0y, t1y)), fminf(t0z, t1z));
    float farv  = fminf(fminf(fmaxf(t0x, t1x), fmaxf(t0y, t1y)), fmaxf(t0z, t1z));
    if (farv < nearv) { nearv = 1e9f; farv = 1e9f; }
    nearv = fmaxf(nearv, 0.05f);
    const float span = farv - nearv;
    const float db = span * (1.0f / 64.0f);   // coarse bin width (constant)

    // ---- CDF: lane owns weights {2l, 2l+1} -> intervals 2l, 2l+1 local ----
    const float2 wpair = *reinterpret_cast<const float2*>(
        wc + (size_t)ray * T0 + 2 * lane);
    const float wa = wpair.x + 0.01f;
    const float wb = wpair.y + 0.01f;
    const float pair = wa + wb;

    float incl = pair;
    #pragma unroll
    for (int o = 1; o < 32; o <<= 1) {
        float v = __shfl_up_sync(FULL, incl, o);
        if (lane >= o) incl += v;
    }
    float excl = __shfl_up_sync(FULL, incl, 1);
    if (lane == 0) excl = 0.0f;
    const float inv_tot = frcp(__shfl_sync(FULL, incl, 31));

    const float c_base = fminf(excl * inv_tot, 1.0f);          // C[2l]
    const float c_mid  = fminf((excl + wa) * inv_tot, 1.0f);   // C[2l+1]
    const float c_end  = fminf(incl * inv_tot, 1.0f);          // C[2l+2]

    float* zed = s_zed[warp];

    // ---- scatter fine edges: interval k covers u in [C[k], C[k+1]) ----
    #pragma unroll
    for (int h = 0; h < 2; ++h) {
        const int k = 2 * lane + h;
        const float c0 = (h == 0) ? c_base : c_mid;
        const float c1 = (h == 0) ? c_mid : c_end;

        int j0 = (int)ceilf(fmaf(129.0f, c0, -0.5f));
        int j1 = (k == 63) ? 129 : (int)ceilf(fmaf(129.0f, c1, -0.5f));
        j0 = max(j0, 0);
        j1 = min(j1, 129);

        const float inv_den = frcp(fmaxf(c1 - c0, 1e-12f));
        const float b0 = fmaf(db, (float)k, nearv);

        for (int j = j0; j < j1; ++j) {
            const float u = (j + 0.5f) * (1.0f / 129.0f);
            float t = fminf(fmaxf((u - c0) * inv_den, 0.0f), 1.0f);
            zed[j] = fmaf(t, db, b0);
        }
    }
    __syncwarp();

    // ---- blocked compositing: lane owns samples 4l..4l+3 ----
    const float4 z4 = *reinterpret_cast<const float4*>(&zed[4 * lane]);
    const float ztop = zed[TF];                         // zed[128], broadcast
    const float znxt = __shfl_down_sync(FULL, z4.x, 1); // next lane's first edge
    const float e4 = (lane == 31) ? ztop : znxt;

    const float4 sg4 = *reinterpret_cast<const float4*>(
        sigmas + (size_t)ray * TF + 4 * lane);

    const float q0 = sg4.x * (z4.y - z4.x);
    const float q1 = sg4.y * (z4.z - z4.y);
    const float q2 = sg4.z * (z4.w - z4.z);
    const float q3 = sg4.w * (e4   - z4.w);

    const float p1 = q0;
    const float p2 = q0 + q1;
    const float p3 = p2 + q2;
    const float Tl = p3 + q3;               // lane-local optical depth

    // single additive warp scan over lane totals
    float iS = Tl;
    #pragma unroll
    for (int o = 1; o < 32; o <<= 1) {
        float v = __shfl_up_sync(FULL, iS, o);
        if (lane >= o) iS += v;
    }
    float S0 = __shfl_up_sync(FULL, iS, 1);
    if (lane == 0) S0 = 0.0f;

    const float E0 = __expf(-S0);
    const float E1 = __expf(-(S0 + p1));
    const float E2 = __expf(-(S0 + p2));
    const float E3 = __expf(-(S0 + p3));
    const float E4 = __expf(-(S0 + Tl));

    const float w0 = E0 - E1;
    const float w1 = E1 - E2;
    const float w2 = E2 - E3;
    const float w3 = E3 - E4;

    const float zm0 = 0.5f * (z4.x + z4.y);
    const float zm1 = 0.5f * (z4.y + z4.z);
    const float zm2 = 0.5f * (z4.z + z4.w);
    const float zm3 = 0.5f * (z4.w + e4);

    float dep = w0 * zm0 + w1 * zm1 + w2 * zm2 + w3 * zm3;

    // ---- rgb: 3x LDG.128, compile-time channel mapping ----
    const float4* rg4 = reinterpret_cast<const float4*>(
        rgbs + (size_t)ray * TF * 3) + 3 * lane;
    const float4 f0 = rg4[0];
    const float4 f1 = rg4[1];
    const float4 f2 = rg4[2];

    float img0 = w0 * f0.x + w1 * f0.w + w2 * f1.z + w3 * f2.y;
    float img1 = w0 * f0.y + w1 * f1.x + w2 * f1.w + w3 * f2.z;
    float img2 = w0 * f0.z + w1 * f1.y + w2 * f2.x + w3 * f2.w;

    // ---- contraction + packed xyz stores (3x STG.128) ----
    float c0x, c0y, c0z, c1x, c1y, c1z, c2x, c2y, c2z, c3x, c3y, c3z;
    contract_pt(zm0, ox, oy, oz, dx, dy, dz, c0x, c0y, c0z);
    contract_pt(zm1, ox, oy, oz, dx, dy, dz, c1x, c1y, c1z);
    contract_pt(zm2, ox, oy, oz, dx, dy, dz, c2x, c2y, c2z);
    contract_pt(zm3, ox, oy, oz, dx, dy, dz, c3x, c3y, c3z);

    const size_t base = (size_t)ray * OUTW;
    float4* xo4 = reinterpret_cast<float4*>(out + base + 4) + 3 * lane;
    xo4[0] = make_float4(c0x, c0y, c0z, c1x);
    xo4[1] = make_float4(c1y, c1z, c2x, c2y);
    xo4[2] = make_float4(c2z, c3x, c3y, c3z);

    // ---- warp reduction for image + depth ----
    #pragma unroll
    for (int o = 16; o > 0; o >>= 1) {
        img0 += __shfl_down_sync(FULL, img0, o);
        img1 += __shfl_down_sync(FULL, img1, o);
        img2 += __shfl_down_sync(FULL, img2, o);
        dep  += __shfl_down_sync(FULL, dep,  o);
    }
    if (lane == 0) {
        float4 head = make_float4(img0, img1, img2, dep);
        *reinterpret_cast<float4*>(out + base) = head;
    }
}

extern "C" void kernel_launch(void* const* d_in, const int* in_sizes, int n_in,
                              void* d_out, int out_size)
{
    const float* rays_o = (const float*)d_in[0];
    const float* rays_d = (const float*)d_in[1];
    const float* aabb   = (const float*)d_in[2];
    const float* wc     = (const float*)d_in[3];
    const float* sigmas = (const float*)d_in[4];
    const float* rgbs   = (const float*)d_in[5];
    float* out = (float*)d_out;

    const int N = in_sizes[0] / 3;   // rays_o has N*3 elements
    const int blocks = (N + WPB - 1) / WPB;
    nerf_render_kernel<<<blocks, WPB * 32>>>(
        rays_o, rays_d, aabb, wc, sigmas, rgbs, out, N);
}